// round 1
// baseline (speedup 1.0000x reference)
#include <cuda_runtime.h>

#define K_TOTAL 100000
#define KC      256
#define NB      ((K_TOTAL + KC - 1) / KC)   // 391
#define SEQ     64
#define G4      200                          // 4*H
#define HID     50
#define SG      (SEQ * G4)                   // 12800

// Scratch (device globals: allocation-free per harness rules)
__device__ float g_partial[NB * SG];         // ~20 MB
__device__ float g_gates[SG];

typedef unsigned long long ull;

__device__ __forceinline__ ull pack2(float a, float b) {
    ull r; asm("mov.b64 %0, {%1, %2};" : "=l"(r) : "f"(a), "f"(b)); return r;
}
__device__ __forceinline__ ull packdup(float a) {
    ull r; asm("mov.b64 %0, {%1, %1};" : "=l"(r) : "f"(a)); return r;
}
__device__ __forceinline__ void fma2(ull& d, ull a, ull b) {
    asm("fma.rn.f32x2 %0, %1, %2, %0;" : "+l"(d) : "l"(a), "l"(b));
}
__device__ __forceinline__ float lo32(ull v) { return __uint_as_float((unsigned)(v & 0xffffffffu)); }
__device__ __forceinline__ float hi32(ull v) { return __uint_as_float((unsigned)(v >> 32)); }

// ---------------------------------------------------------------------------
// Phase A: split-K GEMM partials. C_partial[b][s][g] = sum_{k in chunk b} x[s][k]*Wi[k][g]
// Block: 200 threads, thread t -> (gq = t%50 owning gates 4gq..4gq+3,
//                                  sh = t/50 owning s = 16sh..16sh+15)
// ---------------------------------------------------------------------------
__global__ void __launch_bounds__(200, 2) gemm_partial(
    const float* __restrict__ x, const float* __restrict__ Wi)
{
    extern __shared__ float xs[];   // KC*64 floats, [j][s] transposed, 16B-swizzled
    const int t  = threadIdx.x;
    const int k0 = blockIdx.x * KC;

    // ---- load x chunk: 4s x 4j register transpose, swizzled STS.128 ----
    for (int tile = t; tile < (KC / 4) * 16; tile += 200) {
        const int tj = tile & (KC / 4 - 1);   // j-group 0..63
        const int ts = tile >> 6;             // s-group 0..15
        const int jg = tj * 4;
        float4 rv[4];
        #pragma unroll
        for (int u = 0; u < 4; u++) {
            const int s  = ts * 4 + u;
            const int gj = k0 + jg;
            const float* px = x + (size_t)s * K_TOTAL + gj;
            if (gj + 3 < K_TOTAL) {
                rv[u] = *(const float4*)px;
            } else {
                float a = (gj + 0 < K_TOTAL) ? px[0] : 0.f;
                float b = (gj + 1 < K_TOTAL) ? px[1] : 0.f;
                float c = (gj + 2 < K_TOTAL) ? px[2] : 0.f;
                float d = (gj + 3 < K_TOTAL) ? px[3] : 0.f;
                rv[u] = make_float4(a, b, c, d);
            }
        }
        const float* rf = reinterpret_cast<const float*>(rv);
        #pragma unroll
        for (int v = 0; v < 4; v++) {
            const int j    = jg + v;
            const int idx4 = j * 16 + (ts ^ (j & 15));
            float4 c4 = make_float4(rf[0 * 4 + v], rf[1 * 4 + v], rf[2 * 4 + v], rf[3 * 4 + v]);
            *(float4*)(xs + idx4 * 4) = c4;
        }
    }
    __syncthreads();

    const int gq = t % 50;
    const int sh = t / 50;            // 0..3

    ull acc[4][8];
    #pragma unroll
    for (int a = 0; a < 4; a++)
        #pragma unroll
        for (int b = 0; b < 8; b++) acc[a][b] = 0ull;

    const float* wrow = Wi + (size_t)k0 * G4 + gq * 4;
    const int rem  = K_TOTAL - k0;
    const int jend = rem < KC ? rem : KC;

    #pragma unroll 4
    for (int j = 0; j < jend; j++) {
        const float4 w4 = *(const float4*)(wrow + (size_t)j * G4);
        const ull wp0 = packdup(w4.x), wp1 = packdup(w4.y);
        const ull wp2 = packdup(w4.z), wp3 = packdup(w4.w);
        const int jm = j & 15;
        const int jb = j * 16;
        #pragma unroll
        for (int m = 0; m < 4; m++) {
            const int idx4 = jb + ((sh * 4 + m) ^ jm);
            const ulonglong2 xp = *(const ulonglong2*)(xs + idx4 * 4);
            fma2(acc[0][2 * m],     xp.x, wp0);
            fma2(acc[1][2 * m],     xp.x, wp1);
            fma2(acc[2][2 * m],     xp.x, wp2);
            fma2(acc[3][2 * m],     xp.x, wp3);
            fma2(acc[0][2 * m + 1], xp.y, wp0);
            fma2(acc[1][2 * m + 1], xp.y, wp1);
            fma2(acc[2][2 * m + 1], xp.y, wp2);
            fma2(acc[3][2 * m + 1], xp.y, wp3);
        }
    }

    float* pout = g_partial + (size_t)blockIdx.x * SG;
    #pragma unroll
    for (int p = 0; p < 8; p++) {
        const int s0 = sh * 16 + p * 2;     // pair (s0, s0+1)
        float4 o0 = make_float4(lo32(acc[0][p]), lo32(acc[1][p]), lo32(acc[2][p]), lo32(acc[3][p]));
        float4 o1 = make_float4(hi32(acc[0][p]), hi32(acc[1][p]), hi32(acc[2][p]), hi32(acc[3][p]));
        *(float4*)(pout + (size_t)s0 * G4 + gq * 4)       = o0;
        *(float4*)(pout + (size_t)(s0 + 1) * G4 + gq * 4) = o1;
    }
}

// ---------------------------------------------------------------------------
// Phase B: deterministic split-K reduce + biases
// ---------------------------------------------------------------------------
__global__ void reduce_bias(const float* __restrict__ bi, const float* __restrict__ bh)
{
    const int idx = blockIdx.x * blockDim.x + threadIdx.x;   // 0..12799
    if (idx >= SG) return;
    float s0 = 0.f, s1 = 0.f, s2 = 0.f, s3 = 0.f;
    int b = 0;
    for (; b + 3 < NB; b += 4) {
        s0 += g_partial[(size_t)(b + 0) * SG + idx];
        s1 += g_partial[(size_t)(b + 1) * SG + idx];
        s2 += g_partial[(size_t)(b + 2) * SG + idx];
        s3 += g_partial[(size_t)(b + 3) * SG + idx];
    }
    for (; b < NB; b++) s0 += g_partial[(size_t)b * SG + idx];
    const int g = idx % G4;
    g_gates[idx] = (s0 + s1) + (s2 + s3) + bi[g] + bh[g];
}

// ---------------------------------------------------------------------------
// Phase C: sequential LSTM recurrence, one block.
// ---------------------------------------------------------------------------
__device__ __forceinline__ float fast_sigmoid(float v) {
    return 1.f / (1.f + __expf(-v));
}
__device__ __forceinline__ float fast_tanh(float v) {
    return 2.f / (1.f + __expf(-2.f * v)) - 1.f;
}

__global__ void __launch_bounds__(224) lstm_kernel(const float* __restrict__ Wh,
                                                   float* __restrict__ out)
{
    __shared__ __align__(16) float hbuf[56];
    __shared__ float gbuf[G4];
    const int t = threadIdx.x;

    ull wp[25];
    if (t < G4) {
        #pragma unroll
        for (int kk = 0; kk < 25; kk++) {
            float w0 = Wh[(2 * kk + 0) * G4 + t];
            float w1 = Wh[(2 * kk + 1) * G4 + t];
            wp[kk] = pack2(w0, w1);
        }
    }
    if (t < 56) hbuf[t] = 0.f;
    float c = 0.f;
    __syncthreads();

    for (int step = 0; step < SEQ; step++) {
        if (t < G4) {
            const float pre = g_gates[step * G4 + t];
            ull acc = 0ull;
            #pragma unroll
            for (int kk = 0; kk < 25; kk++) {
                const ull hp = *(const ull*)(hbuf + 2 * kk);
                fma2(acc, hp, wp[kk]);
            }
            gbuf[t] = pre + lo32(acc) + hi32(acc);
        }
        __syncthreads();
        if (t < HID) {
            const float i = fast_sigmoid(gbuf[t]);
            const float f = fast_sigmoid(gbuf[HID + t]);
            const float g = fast_tanh(gbuf[2 * HID + t]);
            const float o = fast_sigmoid(gbuf[3 * HID + t]);
            c = f * c + i * g;
            hbuf[t] = o * fast_tanh(c);
        }
        __syncthreads();
    }
    if (t < HID) out[t] = hbuf[t];
}

// ---------------------------------------------------------------------------
extern "C" void kernel_launch(void* const* d_in, const int* in_sizes, int n_in,
                              void* d_out, int out_size)
{
    const float* x  = (const float*)d_in[0];
    const float* Wi = (const float*)d_in[1];
    const float* bi = (const float*)d_in[2];
    const float* Wh = (const float*)d_in[3];
    const float* bh = (const float*)d_in[4];
    float* out = (float*)d_out;

    (void)in_sizes; (void)n_in; (void)out_size;

    // 64 KB dynamic smem for the x tile (above the 48 KB default) — not an
    // allocation, just a function attribute; idempotent and capture-safe.
    cudaFuncSetAttribute(gemm_partial, cudaFuncAttributeMaxDynamicSharedMemorySize,
                         KC * 64 * 4);

    gemm_partial<<<NB, 200, KC * 64 * 4>>>(x, Wi);
    reduce_bias<<<SG / 128, 128>>>(bi, bh);
    lstm_kernel<<<1, 224>>>(Wh, out);
}

// round 2
// speedup vs baseline: 1.0018x; 1.0018x over previous
#include <cuda_runtime.h>

#define K_TOTAL 100000
#define KC      256
#define NB      ((K_TOTAL + KC - 1) / KC)   // 391
#define SEQ     64
#define G4      200                          // 4*H
#define HID     50
#define SG      (SEQ * G4)                   // 12800

#define RGROUPS 16
#define RSPAN   25                            // 16*25 = 400 >= 391

// Scratch (device globals: allocation-free per harness rules)
__device__ float g_partial[NB * SG];          // ~20 MB
__device__ float g_p2[RGROUPS * SG];          // 800 KB
__device__ float g_gates[SG];

typedef unsigned long long ull;

__device__ __forceinline__ ull pack2(float a, float b) {
    ull r; asm("mov.b64 %0, {%1, %2};" : "=l"(r) : "f"(a), "f"(b)); return r;
}
__device__ __forceinline__ ull packdup(float a) {
    ull r; asm("mov.b64 %0, {%1, %1};" : "=l"(r) : "f"(a)); return r;
}
__device__ __forceinline__ void fma2(ull& d, ull a, ull b) {
    asm("fma.rn.f32x2 %0, %1, %2, %0;" : "+l"(d) : "l"(a), "l"(b));
}
__device__ __forceinline__ float lo32(ull v) { return __uint_as_float((unsigned)(v & 0xffffffffu)); }
__device__ __forceinline__ float hi32(ull v) { return __uint_as_float((unsigned)(v >> 32)); }

// ---------------------------------------------------------------------------
// Phase A: split-K GEMM partials.
// 400 threads: thread t -> gq = t%50 (gates 4gq..4gq+3), sh = t/50 (s = 8sh..8sh+7)
// acc[g][spair]: 4 g-columns x 4 s-pairs (f32x2) = 16 ull = 32 regs.
// Wi rows double-buffer-prefetched 4 j ahead to cover DRAM latency.
// ---------------------------------------------------------------------------
__global__ void __launch_bounds__(400, 2) gemm_partial(
    const float* __restrict__ x, const float* __restrict__ Wi)
{
    extern __shared__ float xs[];   // KC*64 floats, [j][s] transposed, 16B-swizzled
    const int t  = threadIdx.x;
    const int k0 = blockIdx.x * KC;

    // ---- load x chunk: 4s x 4j register transpose, swizzled STS.128 ----
    for (int tile = t; tile < (KC / 4) * 16; tile += 400) {
        const int tj = tile & (KC / 4 - 1);   // j-group 0..63
        const int ts = tile >> 6;             // s-group 0..15
        const int jg = tj * 4;
        float4 rv[4];
        #pragma unroll
        for (int u = 0; u < 4; u++) {
            const int s  = ts * 4 + u;
            const int gj = k0 + jg;
            const float* px = x + (size_t)s * K_TOTAL + gj;
            if (gj + 3 < K_TOTAL) {
                rv[u] = *(const float4*)px;
            } else {
                float a = (gj + 0 < K_TOTAL) ? px[0] : 0.f;
                float b = (gj + 1 < K_TOTAL) ? px[1] : 0.f;
                float c = (gj + 2 < K_TOTAL) ? px[2] : 0.f;
                float d = (gj + 3 < K_TOTAL) ? px[3] : 0.f;
                rv[u] = make_float4(a, b, c, d);
            }
        }
        const float* rf = reinterpret_cast<const float*>(rv);
        #pragma unroll
        for (int v = 0; v < 4; v++) {
            const int j    = jg + v;
            const int idx4 = j * 16 + (ts ^ (j & 15));
            float4 c4 = make_float4(rf[0 * 4 + v], rf[1 * 4 + v], rf[2 * 4 + v], rf[3 * 4 + v]);
            *(float4*)(xs + idx4 * 4) = c4;
        }
    }
    __syncthreads();

    const int gq = t % 50;
    const int sh = t / 50;            // 0..7

    ull acc[4][4];
    #pragma unroll
    for (int a = 0; a < 4; a++)
        #pragma unroll
        for (int b = 0; b < 4; b++) acc[a][b] = 0ull;

    const float* wrow = Wi + (size_t)k0 * G4 + gq * 4;
    const int rem  = K_TOTAL - k0;
    const int jend = rem < KC ? rem : KC;    // always a multiple of 4 here

    // prime prefetch buffer with j = 0..3
    float4 wc[4], wn[4];
    #pragma unroll
    for (int u = 0; u < 4; u++)
        wc[u] = *(const float4*)(wrow + (size_t)u * G4);

    const int g0 = (2 * sh) & 15;       // base s-group indices for this thread
    const int g1 = (2 * sh + 1) & 15;

    for (int jb = 0; jb < jend; jb += 4) {
        // prefetch next 4 Wi rows (predicated at the K tail)
        #pragma unroll
        for (int u = 0; u < 4; u++) {
            const int jn = jb + 4 + u;
            wn[u] = (jn < jend) ? *(const float4*)(wrow + (size_t)jn * G4)
                                : make_float4(0.f, 0.f, 0.f, 0.f);
        }
        // compute current 4 j's
        #pragma unroll
        for (int u = 0; u < 4; u++) {
            const int j  = jb + u;
            const int jm = j & 15;
            const int jbase = j * 16;
            const ull wp0 = packdup(wc[u].x), wp1 = packdup(wc[u].y);
            const ull wp2 = packdup(wc[u].z), wp3 = packdup(wc[u].w);
            const ulonglong2 xa = *(const ulonglong2*)(xs + (jbase + (g0 ^ jm)) * 4);
            const ulonglong2 xb = *(const ulonglong2*)(xs + (jbase + (g1 ^ jm)) * 4);
            fma2(acc[0][0], xa.x, wp0);
            fma2(acc[1][0], xa.x, wp1);
            fma2(acc[2][0], xa.x, wp2);
            fma2(acc[3][0], xa.x, wp3);
            fma2(acc[0][1], xa.y, wp0);
            fma2(acc[1][1], xa.y, wp1);
            fma2(acc[2][1], xa.y, wp2);
            fma2(acc[3][1], xa.y, wp3);
            fma2(acc[0][2], xb.x, wp0);
            fma2(acc[1][2], xb.x, wp1);
            fma2(acc[2][2], xb.x, wp2);
            fma2(acc[3][2], xb.x, wp3);
            fma2(acc[0][3], xb.y, wp0);
            fma2(acc[1][3], xb.y, wp1);
            fma2(acc[2][3], xb.y, wp2);
            fma2(acc[3][3], xb.y, wp3);
        }
        #pragma unroll
        for (int u = 0; u < 4; u++) wc[u] = wn[u];
    }

    float* pout = g_partial + (size_t)blockIdx.x * SG;
    #pragma unroll
    for (int p = 0; p < 4; p++) {
        const int s0 = sh * 8 + p * 2;     // pair (s0, s0+1)
        float4 o0 = make_float4(lo32(acc[0][p]), lo32(acc[1][p]), lo32(acc[2][p]), lo32(acc[3][p]));
        float4 o1 = make_float4(hi32(acc[0][p]), hi32(acc[1][p]), hi32(acc[2][p]), hi32(acc[3][p]));
        *(float4*)(pout + (size_t)s0 * G4 + gq * 4)       = o0;
        *(float4*)(pout + (size_t)(s0 + 1) * G4 + gq * 4) = o1;
    }
}

// ---------------------------------------------------------------------------
// Phase B: two-stage deterministic split-K reduce + biases
// ---------------------------------------------------------------------------
__global__ void reduce_stage1()
{
    const int idx = blockIdx.x * blockDim.x + threadIdx.x;   // 0..12799
    const int grp = blockIdx.y;                               // 0..15
    if (idx >= SG) return;
    const int b0   = grp * RSPAN;
    const int bend = (b0 + RSPAN < NB) ? (b0 + RSPAN) : NB;
    float s0 = 0.f, s1 = 0.f, s2 = 0.f, s3 = 0.f;
    int b = b0;
    for (; b + 3 < bend; b += 4) {
        s0 += g_partial[(size_t)(b + 0) * SG + idx];
        s1 += g_partial[(size_t)(b + 1) * SG + idx];
        s2 += g_partial[(size_t)(b + 2) * SG + idx];
        s3 += g_partial[(size_t)(b + 3) * SG + idx];
    }
    for (; b < bend; b++) s0 += g_partial[(size_t)b * SG + idx];
    g_p2[(size_t)grp * SG + idx] = (s0 + s1) + (s2 + s3);
}

__global__ void reduce_stage2(const float* __restrict__ bi, const float* __restrict__ bh)
{
    const int idx = blockIdx.x * blockDim.x + threadIdx.x;   // 0..12799
    if (idx >= SG) return;
    float s0 = 0.f, s1 = 0.f, s2 = 0.f, s3 = 0.f;
    #pragma unroll
    for (int b = 0; b < RGROUPS; b += 4) {
        s0 += g_p2[(size_t)(b + 0) * SG + idx];
        s1 += g_p2[(size_t)(b + 1) * SG + idx];
        s2 += g_p2[(size_t)(b + 2) * SG + idx];
        s3 += g_p2[(size_t)(b + 3) * SG + idx];
    }
    const int g = idx % G4;
    g_gates[idx] = (s0 + s1) + (s2 + s3) + bi[g] + bh[g];
}

// ---------------------------------------------------------------------------
// Phase C: sequential LSTM recurrence, one block.
// ---------------------------------------------------------------------------
__device__ __forceinline__ float fast_sigmoid(float v) {
    return 1.f / (1.f + __expf(-v));
}
__device__ __forceinline__ float fast_tanh(float v) {
    return 2.f / (1.f + __expf(-2.f * v)) - 1.f;
}

__global__ void __launch_bounds__(224) lstm_kernel(const float* __restrict__ Wh,
                                                   float* __restrict__ out)
{
    __shared__ __align__(16) float hbuf[56];
    __shared__ float gbuf[G4];
    const int t = threadIdx.x;

    ull wp[25];
    if (t < G4) {
        #pragma unroll
        for (int kk = 0; kk < 25; kk++) {
            float w0 = Wh[(2 * kk + 0) * G4 + t];
            float w1 = Wh[(2 * kk + 1) * G4 + t];
            wp[kk] = pack2(w0, w1);
        }
    }
    if (t < 56) hbuf[t] = 0.f;
    float c = 0.f;
    __syncthreads();

    for (int step = 0; step < SEQ; step++) {
        if (t < G4) {
            const float pre = g_gates[step * G4 + t];
            ull acc = 0ull;
            #pragma unroll
            for (int kk = 0; kk < 25; kk++) {
                const ull hp = *(const ull*)(hbuf + 2 * kk);
                fma2(acc, hp, wp[kk]);
            }
            gbuf[t] = pre + lo32(acc) + hi32(acc);
        }
        __syncthreads();
        if (t < HID) {
            const float i = fast_sigmoid(gbuf[t]);
            const float f = fast_sigmoid(gbuf[HID + t]);
            const float g = fast_tanh(gbuf[2 * HID + t]);
            const float o = fast_sigmoid(gbuf[3 * HID + t]);
            c = f * c + i * g;
            hbuf[t] = o * fast_tanh(c);
        }
        __syncthreads();
    }
    if (t < HID) out[t] = hbuf[t];
}

// ---------------------------------------------------------------------------
extern "C" void kernel_launch(void* const* d_in, const int* in_sizes, int n_in,
                              void* d_out, int out_size)
{
    const float* x  = (const float*)d_in[0];
    const float* Wi = (const float*)d_in[1];
    const float* bi = (const float*)d_in[2];
    const float* Wh = (const float*)d_in[3];
    const float* bh = (const float*)d_in[4];
    float* out = (float*)d_out;

    (void)in_sizes; (void)n_in; (void)out_size;

    cudaFuncSetAttribute(gemm_partial, cudaFuncAttributeMaxDynamicSharedMemorySize,
                         KC * 64 * 4);

    gemm_partial<<<NB, 400, KC * 64 * 4>>>(x, Wi);
    reduce_stage1<<<dim3(SG / 128, RGROUPS), 128>>>();
    reduce_stage2<<<SG / 128, 128>>>(bi, bh);
    lstm_kernel<<<1, 224>>>(Wh, out);
}